// round 10
// baseline (speedup 1.0000x reference)
#include <cuda_runtime.h>
#include <cstdint>

#define N_NODES 500000
#define N_EDGES 16000000
#define BIT_WORDS 15625            // 500000 / 32 exactly
#define BIT_BYTES (BIT_WORDS * 4)  // 62500

// Per-node gain: relu(v[n]) * type_params[type[n]].  2 MB, stays L2-hot.
// ~50% of entries are exactly 0.0f (relu of N(0,1) voltage).
__device__ float    g_gain[N_NODES];
// 1 bit per node: g_gain[n] != 0.  62.5 KB -> fits in SMEM per block.
__device__ unsigned g_bits[BIT_WORDS];

// ---------------------------------------------------------------------------
// Kernel A: node prep. g_gain, zero-bitmap, out[n] = -v + stim + Vrest
// ---------------------------------------------------------------------------
__global__ void node_prep(const float* __restrict__ voltage,
                          const float* __restrict__ stimulus,
                          const int*   __restrict__ ntype,      // int32 (JAX x64 off)
                          const float* __restrict__ v_rest,
                          const float* __restrict__ type_params,
                          float* __restrict__ out,
                          int n)
{
    int i = blockIdx.x * blockDim.x + threadIdx.x;
    float g = 0.0f;
    if (i < n) {
        float v = voltage[i];
        float r = fmaxf(v, 0.0f);
        int t = ntype[i];                 // values in [0,64)
        g = r * __ldg(&type_params[t]);
        g_gain[i] = g;
        out[i] = -v + stimulus[i] + v_rest[i];
    }
    unsigned b = __ballot_sync(0xffffffffu, g != 0.0f);
    if ((threadIdx.x & 31) == 0 && i < n) {
        g_bits[i >> 5] = b;               // warp base i -> word i/32 (< BIT_WORDS)
    }
}

// ---------------------------------------------------------------------------
// Predicated gather: returns g_gain[.] if bit else 0, issuing NO memory
// transaction when bit==0. Non-volatile, no memory clobber -> ptxas may
// freely schedule/batch several of these (MLP), but cannot un-predicate.
// Safe: g_gain is read-only during this kernel.
// ---------------------------------------------------------------------------
__device__ __forceinline__ float pred_gather(int bit, const float* gaddr)
{
    float g;
    asm("{\n\t"
        ".reg .pred p;\n\t"
        "setp.ne.s32 p, %1, 0;\n\t"
        "mov.f32 %0, 0f00000000;\n\t"
        "@p ld.global.nc.f32 %0, [%2];\n\t"
        "}"
        : "=f"(g) : "r"(bit), "l"(gaddr));
    return g;
}

// Predicated no-return atomic: skips the RED lane when the message is zero.
__device__ __forceinline__ void pred_red(float m, float* oaddr)
{
    asm volatile(
        "{\n\t"
        ".reg .pred p;\n\t"
        "setp.neu.f32 p, %0, 0f00000000;\n\t"
        "@p red.global.add.f32 [%1], %0;\n\t"
        "}"
        :: "f"(m), "l"(oaddr) : "memory");
}

// ---------------------------------------------------------------------------
// Kernel B: persistent edge scatter with SMEM zero-bitmap.
// 4 batched predicated gathers (MLP) -> 4 muls -> 4 predicated REDs.
// ---------------------------------------------------------------------------
__global__ void __launch_bounds__(512) edge_scatter(
    const int4*   __restrict__ src4,   // edge_index row 0, int32 x4
    const int4*   __restrict__ dst4,   // edge_index row 1, int32 x4
    const float4* __restrict__ w4,
    float*        __restrict__ out,
    int n_groups)                      // N_EDGES / 4
{
    extern __shared__ unsigned sbits[];

    // Cooperative bitmap load.
    for (int j = threadIdx.x; j < BIT_WORDS; j += blockDim.x)
        sbits[j] = g_bits[j];
    __syncthreads();

    int stride = gridDim.x * blockDim.x;
    for (int i = blockIdx.x * blockDim.x + threadIdx.x; i < n_groups; i += stride) {
        // streamed data: evict-first, don't thrash L2-resident g_gain/out
        int4   s = __ldcs(&src4[i]);
        int4   d = __ldcs(&dst4[i]);
        float4 w = __ldcs(&w4[i]);

        int b0 = (sbits[s.x >> 5] >> (s.x & 31)) & 1;
        int b1 = (sbits[s.y >> 5] >> (s.y & 31)) & 1;
        int b2 = (sbits[s.z >> 5] >> (s.z & 31)) & 1;
        int b3 = (sbits[s.w >> 5] >> (s.w & 31)) & 1;

        // 4 independent predicated gathers (front-batched by ptxas)
        float g0 = pred_gather(b0, &g_gain[s.x]);
        float g1 = pred_gather(b1, &g_gain[s.y]);
        float g2 = pred_gather(b2, &g_gain[s.z]);
        float g3 = pred_gather(b3, &g_gain[s.w]);

        // 4 predicated no-return atomics (m==0 exactly when bit==0)
        pred_red(w.x * g0, &out[d.x]);
        pred_red(w.y * g1, &out[d.y]);
        pred_red(w.z * g2, &out[d.z]);
        pred_red(w.w * g3, &out[d.w]);
    }
}

// ---------------------------------------------------------------------------
// Kernel C: out[n] = out[n] / tau[n]
// ---------------------------------------------------------------------------
__global__ void finalize(const float* __restrict__ tau,
                         float* __restrict__ out,
                         int n)
{
    int i = blockIdx.x * blockDim.x + threadIdx.x;
    if (i < n) {
        out[i] = out[i] / tau[i];
    }
}

// ---------------------------------------------------------------------------
// Launch
//   d_in: 0 voltage, 1 stimulus, 2 neuron_type(i32), 3 edge_index(i32 2xE),
//         4 w, 5 V_i_rest, 6 tau_i, 7 type_params
// ---------------------------------------------------------------------------
extern "C" void kernel_launch(void* const* d_in, const int* in_sizes, int n_in,
                              void* d_out, int out_size)
{
    const float* voltage = (const float*)d_in[0];
    const float* stim    = (const float*)d_in[1];
    const int*   ntype   = (const int*)d_in[2];
    const int*   eidx    = (const int*)d_in[3];
    const float* w       = (const float*)d_in[4];
    const float* vrest   = (const float*)d_in[5];
    const float* tau     = (const float*)d_in[6];
    const float* tparams = (const float*)d_in[7];
    float*       out     = (float*)d_out;

    const int n_nodes = N_NODES;
    const int n_edges = N_EDGES;

    // Allow >48KB dynamic smem for the bitmap kernel (idempotent, host-side).
    cudaFuncSetAttribute(edge_scatter,
                         cudaFuncAttributeMaxDynamicSharedMemorySize,
                         BIT_BYTES);

    // Kernel A
    {
        int threads = 256;
        int blocks = (n_nodes + threads - 1) / threads;
        node_prep<<<blocks, threads>>>(voltage, stim, ntype, vrest, tparams,
                                       out, n_nodes);
    }

    // Kernel B: persistent, 3 blocks/SM (62.5KB smem each), 512 thr/block
    // -> 48 warps/SM for gather-latency hiding.
    {
        const int4*   src4 = (const int4*)(eidx);
        const int4*   dst4 = (const int4*)(eidx + n_edges);
        const float4* w4   = (const float4*)w;
        int n_groups = n_edges / 4;           // 4,000,000 (exact)
        int threads = 512;
        int blocks = 148 * 3;                 // persistent wave
        edge_scatter<<<blocks, threads, BIT_BYTES>>>(src4, dst4, w4, out,
                                                     n_groups);
    }

    // Kernel C
    {
        int threads = 256;
        int blocks = (n_nodes + threads - 1) / threads;
        finalize<<<blocks, threads>>>(tau, out, n_nodes);
    }
}

// round 11
// speedup vs baseline: 1.0661x; 1.0661x over previous
#include <cuda_runtime.h>
#include <cstdint>

#define N_NODES 500000
#define N_EDGES 16000000
#define BIT_WORDS 15625            // 500000 / 32 exactly
#define BIT_BYTES (BIT_WORDS * 4)  // 62500

// Per-node gain: relu(v[n]) * type_params[type[n]].  2 MB, stays L2-hot.
// ~50% of entries are exactly 0.0f (relu of N(0,1) voltage).
__device__ float    g_gain[N_NODES];
// 1 bit per node: g_gain[n] != 0.  62.5 KB -> fits in SMEM per block.
__device__ unsigned g_bits[BIT_WORDS];

// ---------------------------------------------------------------------------
// Kernel A: node prep. g_gain, zero-bitmap, out[n] = -v + stim + Vrest
// ---------------------------------------------------------------------------
__global__ void node_prep(const float* __restrict__ voltage,
                          const float* __restrict__ stimulus,
                          const int*   __restrict__ ntype,      // int32 (JAX x64 off)
                          const float* __restrict__ v_rest,
                          const float* __restrict__ type_params,
                          float* __restrict__ out,
                          int n)
{
    int i = blockIdx.x * blockDim.x + threadIdx.x;
    float g = 0.0f;
    if (i < n) {
        float v = voltage[i];
        float r = fmaxf(v, 0.0f);
        int t = ntype[i];                 // values in [0,64)
        g = r * __ldg(&type_params[t]);
        g_gain[i] = g;
        out[i] = -v + stimulus[i] + v_rest[i];
    }
    unsigned b = __ballot_sync(0xffffffffu, g != 0.0f);
    if ((threadIdx.x & 31) == 0 && i < n) {
        g_bits[i >> 5] = b;               // warp base i -> word i/32 (< BIT_WORDS)
    }
}

// ---------------------------------------------------------------------------
// Predicated gather: returns g_gain[.] if bit else 0, issuing NO memory
// transaction when bit==0. Non-volatile, no memory clobber -> ptxas may
// front-batch several (MLP) but cannot un-predicate them.
// Safe: g_gain is read-only during this kernel.
// ---------------------------------------------------------------------------
__device__ __forceinline__ float pred_gather(int bit, const float* gaddr)
{
    float g;
    asm("{\n\t"
        ".reg .pred p;\n\t"
        "setp.ne.s32 p, %1, 0;\n\t"
        "mov.f32 %0, 0f00000000;\n\t"
        "@p ld.global.nc.f32 %0, [%2];\n\t"
        "}"
        : "=f"(g) : "r"(bit), "l"(gaddr));
    return g;
}

// Predicated no-return atomic, guarded by the EARLY integer bit (ISETP),
// not by an FSETP on the load result (that was R10's regression: the RED
// guard waited 13 extra cycles after the 250-cycle gather).
__device__ __forceinline__ void pred_red_bit(int bit, float m, float* oaddr)
{
    asm volatile(
        "{\n\t"
        ".reg .pred p;\n\t"
        "setp.ne.s32 p, %0, 0;\n\t"
        "@p red.global.add.f32 [%2], %1;\n\t"
        "}"
        :: "r"(bit), "f"(m), "l"(oaddr) : "memory");
}

// ---------------------------------------------------------------------------
// Kernel B: persistent edge scatter with SMEM zero-bitmap.
// 4 front-batched predicated gathers (MLP=4) -> 4 muls -> 4 bit-predicated
// no-return atomics.
// ---------------------------------------------------------------------------
__global__ void __launch_bounds__(256) edge_scatter(
    const int4*   __restrict__ src4,   // edge_index row 0, int32 x4
    const int4*   __restrict__ dst4,   // edge_index row 1, int32 x4
    const float4* __restrict__ w4,
    float*        __restrict__ out,
    int n_groups)                      // N_EDGES / 4
{
    extern __shared__ unsigned sbits[];

    // Cooperative bitmap load.
    for (int j = threadIdx.x; j < BIT_WORDS; j += blockDim.x)
        sbits[j] = g_bits[j];
    __syncthreads();

    int stride = gridDim.x * blockDim.x;
    for (int i = blockIdx.x * blockDim.x + threadIdx.x; i < n_groups; i += stride) {
        // streamed data: evict-first, don't thrash L2-resident g_gain/out
        int4   s = __ldcs(&src4[i]);
        int4   d = __ldcs(&dst4[i]);
        float4 w = __ldcs(&w4[i]);

        int b0 = (sbits[s.x >> 5] >> (s.x & 31)) & 1;
        int b1 = (sbits[s.y >> 5] >> (s.y & 31)) & 1;
        int b2 = (sbits[s.z >> 5] >> (s.z & 31)) & 1;
        int b3 = (sbits[s.w >> 5] >> (s.w & 31)) & 1;

        // 4 independent predicated gathers (front-batched by ptxas)
        float g0 = pred_gather(b0, &g_gain[s.x]);
        float g1 = pred_gather(b1, &g_gain[s.y]);
        float g2 = pred_gather(b2, &g_gain[s.z]);
        float g3 = pred_gather(b3, &g_gain[s.w]);

        // 4 bit-predicated no-return atomics
        pred_red_bit(b0, w.x * g0, &out[d.x]);
        pred_red_bit(b1, w.y * g1, &out[d.y]);
        pred_red_bit(b2, w.z * g2, &out[d.z]);
        pred_red_bit(b3, w.w * g3, &out[d.w]);
    }
}

// ---------------------------------------------------------------------------
// Kernel C: out[n] = out[n] / tau[n]
// ---------------------------------------------------------------------------
__global__ void finalize(const float* __restrict__ tau,
                         float* __restrict__ out,
                         int n)
{
    int i = blockIdx.x * blockDim.x + threadIdx.x;
    if (i < n) {
        out[i] = out[i] / tau[i];
    }
}

// ---------------------------------------------------------------------------
// Launch
//   d_in: 0 voltage, 1 stimulus, 2 neuron_type(i32), 3 edge_index(i32 2xE),
//         4 w, 5 V_i_rest, 6 tau_i, 7 type_params
// ---------------------------------------------------------------------------
extern "C" void kernel_launch(void* const* d_in, const int* in_sizes, int n_in,
                              void* d_out, int out_size)
{
    const float* voltage = (const float*)d_in[0];
    const float* stim    = (const float*)d_in[1];
    const int*   ntype   = (const int*)d_in[2];
    const int*   eidx    = (const int*)d_in[3];
    const float* w       = (const float*)d_in[4];
    const float* vrest   = (const float*)d_in[5];
    const float* tau     = (const float*)d_in[6];
    const float* tparams = (const float*)d_in[7];
    float*       out     = (float*)d_out;

    const int n_nodes = N_NODES;
    const int n_edges = N_EDGES;

    // Allow >48KB dynamic smem for the bitmap kernel (idempotent, host-side).
    cudaFuncSetAttribute(edge_scatter,
                         cudaFuncAttributeMaxDynamicSharedMemorySize,
                         BIT_BYTES);

    // Kernel A
    {
        int threads = 256;
        int blocks = (n_nodes + threads - 1) / threads;
        node_prep<<<blocks, threads>>>(voltage, stim, ntype, vrest, tparams,
                                       out, n_nodes);
    }

    // Kernel B: persistent, 3 blocks/SM (62.5KB smem each), 256 thr/block
    {
        const int4*   src4 = (const int4*)(eidx);
        const int4*   dst4 = (const int4*)(eidx + n_edges);
        const float4* w4   = (const float4*)w;
        int n_groups = n_edges / 4;           // 4,000,000 (exact)
        int threads = 256;
        int blocks = 148 * 3;                 // persistent wave
        edge_scatter<<<blocks, threads, BIT_BYTES>>>(src4, dst4, w4, out,
                                                     n_groups);
    }

    // Kernel C
    {
        int threads = 256;
        int blocks = (n_nodes + threads - 1) / threads;
        finalize<<<blocks, threads>>>(tau, out, n_nodes);
    }
}